// round 1
// baseline (speedup 1.0000x reference)
#include <cuda_runtime.h>
#include <math.h>

// ---------------- static scratch (no allocations allowed) ----------------
// max intermediate: t3 out = 64*8*129*129 = 8,520,192 floats
__device__ float g_bufA[8520192];
__device__ float g_bufB[8520192];
__device__ float g_cnorm[512];
__device__ float g_partial[256];   // 225 VQ block partial sums (fixed-order reduce later)

#define LRELU_SLOPE 0.01f

// ---------------- direct conv (NCHW, OIHW weights), per-block shared weights ----
// grid: x = ceil(HOUT*WOUT/256), y = COUT, z = B
template<int CIN, int K, int S, int P, int ACT>
__global__ void conv2d_k(const float* __restrict__ in, const float* __restrict__ w,
                         const float* __restrict__ bias, float* __restrict__ out,
                         int HIN, int WIN, int HOUT, int WOUT)
{
    const int co = blockIdx.y;
    const int nb = blockIdx.z;
    const int COUT = gridDim.y;

    __shared__ float sw[CIN * K * K];
    __shared__ float sb;
    for (int i = threadIdx.x; i < CIN * K * K; i += blockDim.x)
        sw[i] = w[co * CIN * K * K + i];
    if (threadIdx.x == 0) sb = bias[co];
    __syncthreads();

    int sp = blockIdx.x * blockDim.x + threadIdx.x;
    if (sp >= HOUT * WOUT) return;
    int oh = sp / WOUT, ow = sp - oh * WOUT;

    const float* ib = in + (size_t)nb * CIN * HIN * WIN;
    float acc = sb;
    #pragma unroll 4
    for (int ci = 0; ci < CIN; ci++) {
        #pragma unroll
        for (int kh = 0; kh < K; kh++) {
            int ih = oh * S - P + kh;
            if (P > 0 && (ih < 0 || ih >= HIN)) continue;
            #pragma unroll
            for (int kw = 0; kw < K; kw++) {
                int iw = ow * S - P + kw;
                if (P > 0 && (iw < 0 || iw >= WIN)) continue;
                acc = fmaf(ib[(ci * HIN + ih) * WIN + iw], sw[(ci * K + kh) * K + kw], acc);
            }
        }
    }
    if (ACT == 1) acc = acc >= 0.f ? acc : LRELU_SLOPE * acc;
    out[(((size_t)nb * COUT + co) * HOUT + oh) * WOUT + ow] = acc;
}

// ---------------- transposed conv k=4 s=2 (gather form), weights [CIN,COUT,4,4] ----
// out[oh,ow] = bias + sum over kh in {oh&1, oh&1+2}, kw in {ow&1, ow&1+2},
//              ih=(oh-kh)/2, iw=(ow-kw)/2 valid -> sum_ci in[ci,ih,iw]*w[ci,co,kh,kw]
template<int CIN, int ACT>
__global__ void tconv_k(const float* __restrict__ in, const float* __restrict__ w,
                        const float* __restrict__ bias, float* __restrict__ out,
                        int HIN, int WIN, int HOUT, int WOUT)
{
    const int co = blockIdx.y;
    const int nb = blockIdx.z;
    const int COUT = gridDim.y;

    __shared__ float sw[CIN * 16];
    __shared__ float sb;
    for (int i = threadIdx.x; i < CIN * 16; i += blockDim.x) {
        int ci = i >> 4, r = i & 15;
        sw[i] = w[(ci * COUT + co) * 16 + r];
    }
    if (threadIdx.x == 0) sb = bias[co];
    __syncthreads();

    int sp = blockIdx.x * blockDim.x + threadIdx.x;
    if (sp >= HOUT * WOUT) return;
    int oh = sp / WOUT, ow = sp - oh * WOUT;

    const float* ib = in + (size_t)nb * CIN * HIN * WIN;
    float acc = sb;
    #pragma unroll
    for (int dkh = 0; dkh < 2; dkh++) {
        int kh = (oh & 1) + 2 * dkh;
        int t = oh - kh;
        if (t < 0) continue;
        int ih = t >> 1;
        if (ih >= HIN) continue;
        #pragma unroll
        for (int dkw = 0; dkw < 2; dkw++) {
            int kw = (ow & 1) + 2 * dkw;
            int u = ow - kw;
            if (u < 0) continue;
            int iw = u >> 1;
            if (iw >= WIN) continue;
            #pragma unroll 4
            for (int ci = 0; ci < CIN; ci++)
                acc = fmaf(ib[(ci * HIN + ih) * WIN + iw], sw[ci * 16 + kh * 4 + kw], acc);
        }
    }
    if (ACT == 1) acc = acc >= 0.f ? acc : LRELU_SLOPE * acc;
    if (ACT == 2) acc = tanhf(acc);
    out[(((size_t)nb * COUT + co) * HOUT + oh) * WOUT + ow] = acc;
}

// ---------------- codebook squared norms ----------------
__global__ void cnorm_k(const float* __restrict__ cb)
{
    int c = blockIdx.x * blockDim.x + threadIdx.x;
    if (c < 512) {
        float s = 0.f;
        #pragma unroll
        for (int d = 0; d < 64; d++) {
            float v = cb[c * 64 + d];
            s = fmaf(v, v, s);
        }
        g_cnorm[c] = s;
    }
}

// ---------------- VQ: argmin_c ||f-c||^2 over 512 codes, D=64 ----------------
// e5: [64,64,30,30] NCHW (latent channels = D). z: same layout, quantized.
// Exactly 57600 positions = 225 blocks * 256 threads.
__global__ void vq_k(const float* __restrict__ e5, const float* __restrict__ cb,
                     float* __restrict__ z)
{
    __shared__ float scb[128 * 64];   // 32 KB codebook chunk
    __shared__ float scn[128];
    __shared__ float red[256];

    int n  = blockIdx.x * 256 + threadIdx.x;      // position id, always < 57600
    int b  = n / 900;
    int sp = n - b * 900;

    float lat[64];
    float fnorm = 0.f;
    #pragma unroll
    for (int d = 0; d < 64; d++) {
        float v = e5[((size_t)(b * 64 + d)) * 900 + sp];
        lat[d] = v;
        fnorm = fmaf(v, v, fnorm);
    }

    float best = -1e30f;
    int bi = 0;
    for (int cbase = 0; cbase < 512; cbase += 128) {
        const float4* src = (const float4*)(cb + cbase * 64);
        float4* dst = (float4*)scb;
        for (int i = threadIdx.x; i < 2048; i += 256) dst[i] = src[i];
        if (threadIdx.x < 128) scn[threadIdx.x] = g_cnorm[cbase + threadIdx.x];
        __syncthreads();

        for (int c = 0; c < 128; c++) {
            const float* cp = &scb[c * 64];
            float dot = 0.f;
            #pragma unroll
            for (int d = 0; d < 64; d++) dot = fmaf(lat[d], cp[d], dot);
            float score = dot - 0.5f * scn[c];   // argmax score == argmin distance
            if (score > best) { best = score; bi = cbase + c; }
        }
        __syncthreads();
    }

    // write quantized vector (forward value of straight-through = q)
    const float* cq = cb + bi * 64;
    #pragma unroll
    for (int d = 0; d < 64; d++)
        z[((size_t)(b * 64 + d)) * 900 + sp] = cq[d];

    // loss partial: d2 = ||f||^2 - 2*dot + ||c||^2 = fnorm - 2*best
    float d2 = fnorm - 2.f * best;
    red[threadIdx.x] = d2;
    __syncthreads();
    for (int s = 128; s > 0; s >>= 1) {
        if (threadIdx.x < s) red[threadIdx.x] += red[threadIdx.x + s];
        __syncthreads();
    }
    if (threadIdx.x == 0) g_partial[blockIdx.x] = red[0];
}

// ---------------- deterministic loss finalize ----------------
__global__ void loss_fin(float* __restrict__ out, int out_size)
{
    __shared__ float red[256];
    float v = (threadIdx.x < 225) ? g_partial[threadIdx.x] : 0.f;
    red[threadIdx.x] = v;
    __syncthreads();
    for (int s = 128; s > 0; s >>= 1) {
        if (threadIdx.x < s) red[threadIdx.x] += red[threadIdx.x + s];
        __syncthreads();
    }
    if (threadIdx.x == 0) {
        // vq_loss = commitment*0.25 + embedding = 1.25 * mean((q-lat)^2)
        out[out_size - 1] = 1.25f * red[0] / 3686400.0f;
    }
}

// ---------------- launch ----------------
extern "C" void kernel_launch(void* const* d_in, const int* in_sizes, int n_in,
                              void* d_out, int out_size)
{
    (void)in_sizes; (void)n_in;
    const float* x   = (const float*)d_in[0];
    const float* ew1 = (const float*)d_in[1];  const float* eb1 = (const float*)d_in[2];
    const float* ew2 = (const float*)d_in[3];  const float* eb2 = (const float*)d_in[4];
    const float* ew3 = (const float*)d_in[5];  const float* eb3 = (const float*)d_in[6];
    const float* ew4 = (const float*)d_in[7];  const float* eb4 = (const float*)d_in[8];
    const float* ew5 = (const float*)d_in[9];  const float* eb5 = (const float*)d_in[10];
    const float* dw1 = (const float*)d_in[11]; const float* db1 = (const float*)d_in[12];
    const float* dw2 = (const float*)d_in[13]; const float* db2 = (const float*)d_in[14];
    const float* dw3 = (const float*)d_in[15]; const float* db3 = (const float*)d_in[16];
    const float* dw4 = (const float*)d_in[17]; const float* db4 = (const float*)d_in[18];
    const float* cbk = (const float*)d_in[19];
    float* out = (float*)d_out;

    float *bufA, *bufB;
    cudaGetSymbolAddress((void**)&bufA, g_bufA);
    cudaGetSymbolAddress((void**)&bufB, g_bufB);

    const int B = 64;
    const int T = 256;

    // ---- encoder ----
    // conv1: [64,1,256,256] -> [64,8,127,127], k4 s2
    conv2d_k<1, 4, 2, 0, 1><<<dim3((127*127 + T-1)/T, 8, B), T>>>(x, ew1, eb1, bufA, 256, 256, 127, 127);
    // conv2: -> [64,16,62,62]
    conv2d_k<8, 4, 2, 0, 1><<<dim3((62*62 + T-1)/T, 16, B), T>>>(bufA, ew2, eb2, bufB, 127, 127, 62, 62);
    // conv3: -> [64,32,30,30]
    conv2d_k<16, 4, 2, 0, 1><<<dim3((30*30 + T-1)/T, 32, B), T>>>(bufB, ew3, eb3, bufA, 62, 62, 30, 30);
    // conv4: 3x3 p1 -> [64,32,30,30]
    conv2d_k<32, 3, 1, 1, 1><<<dim3((30*30 + T-1)/T, 32, B), T>>>(bufA, ew4, eb4, bufB, 30, 30, 30, 30);
    // conv5: 1x1 -> [64,64,30,30]
    conv2d_k<32, 1, 1, 0, 1><<<dim3((30*30 + T-1)/T, 64, B), T>>>(bufB, ew5, eb5, bufA, 30, 30, 30, 30);

    // ---- VQ ----
    cnorm_k<<<2, 256>>>(cbk);
    vq_k<<<225, 256>>>(bufA, cbk, bufB);   // z -> bufB

    // ---- decoder ----
    // d1: 3x3 p1, 64->32 ch, [64,32,30,30]
    conv2d_k<64, 3, 1, 1, 1><<<dim3((30*30 + T-1)/T, 32, B), T>>>(bufB, dw1, db1, bufA, 30, 30, 30, 30);
    // t2: tconv 32->16, 30 -> 63
    tconv_k<32, 1><<<dim3((63*63 + T-1)/T, 16, B), T>>>(bufA, dw2, db2, bufB, 30, 30, 63, 63);
    // t3: tconv 16->8, 63 -> 129
    tconv_k<16, 1><<<dim3((129*129 + T-1)/T, 8, B), T>>>(bufB, dw3, db3, bufA, 63, 63, 129, 129);
    // t4: tconv 8->1, 129 -> 260, tanh, straight to d_out
    tconv_k<8, 2><<<dim3((260*260 + T-1)/T, 1, B), T>>>(bufA, dw4, db4, out, 129, 129, 260, 260);

    // ---- loss scalar ----
    loss_fin<<<1, 256>>>(out, out_size);
}

// round 2
// speedup vs baseline: 2.2775x; 2.2775x over previous
#include <cuda_runtime.h>
#include <math.h>

// ---------------- static scratch (no allocations allowed) ----------------
__device__ float g_bufA[8520192];
__device__ float g_bufB[8520192];
__device__ float g_cnorm[512];
__device__ float g_partial[256];

#define LRELU_SLOPE 0.01f

// ================= conv2d, register-tiled over COUT =================
// Each thread: one spatial position, CT output channels.
// Weights staged in shared as [tap][co] so the co-loop reads are float4.
template<int CIN, int COUT, int CT, int K, int S, int P, int ACT>
__global__ void conv_t(const float* __restrict__ in, const float* __restrict__ w,
                       const float* __restrict__ bias, float* __restrict__ out,
                       int HIN, int WIN, int HOUT, int WOUT)
{
    const int cob = blockIdx.y * CT;
    const int nb  = blockIdx.z;

    __shared__ __align__(16) float sw[CIN * K * K * CT];
    __shared__ float sb[CT];
    for (int i = threadIdx.x; i < CIN * K * K * CT; i += blockDim.x) {
        int tap = i / CT, co = i - tap * CT;
        sw[i] = w[(size_t)(cob + co) * CIN * K * K + tap];
    }
    if (threadIdx.x < CT) sb[threadIdx.x] = bias[cob + threadIdx.x];
    __syncthreads();

    int sp = blockIdx.x * blockDim.x + threadIdx.x;
    if (sp >= HOUT * WOUT) return;
    int oh = sp / WOUT, ow = sp - oh * WOUT;

    const float* ib = in + (size_t)nb * CIN * HIN * WIN;
    float acc[CT];
    #pragma unroll
    for (int c = 0; c < CT; c++) acc[c] = sb[c];

    for (int ci = 0; ci < CIN; ci++) {
        #pragma unroll
        for (int kh = 0; kh < K; kh++) {
            int ih = oh * S - P + kh;
            if (P > 0 && (ih < 0 || ih >= HIN)) continue;
            #pragma unroll
            for (int kw = 0; kw < K; kw++) {
                int iw = ow * S - P + kw;
                if (P > 0 && (iw < 0 || iw >= WIN)) continue;
                float v = ib[(ci * HIN + ih) * WIN + iw];
                if (CT >= 4) {
                    const float4* wp = (const float4*)&sw[((ci * K + kh) * K + kw) * CT];
                    #pragma unroll
                    for (int c4 = 0; c4 < CT / 4; c4++) {
                        float4 wv = wp[c4];
                        acc[c4*4+0] = fmaf(v, wv.x, acc[c4*4+0]);
                        acc[c4*4+1] = fmaf(v, wv.y, acc[c4*4+1]);
                        acc[c4*4+2] = fmaf(v, wv.z, acc[c4*4+2]);
                        acc[c4*4+3] = fmaf(v, wv.w, acc[c4*4+3]);
                    }
                } else {
                    const float* wp = &sw[((ci * K + kh) * K + kw) * CT];
                    #pragma unroll
                    for (int c = 0; c < CT; c++) acc[c] = fmaf(v, wp[c], acc[c]);
                }
            }
        }
    }
    #pragma unroll
    for (int c = 0; c < CT; c++) {
        float a = acc[c];
        if (ACT == 1) a = a >= 0.f ? a : LRELU_SLOPE * a;
        out[(((size_t)nb * COUT + cob + c) * HOUT + oh) * WOUT + ow] = a;
    }
}

// ================= transposed conv k=4 s=2 (gather), tiled over COUT ======
// weights [CIN, COUT, 4, 4]; each output has exactly <=2x2 valid taps.
template<int CIN, int COUT, int CT, int ACT>
__global__ void tconv_t(const float* __restrict__ in, const float* __restrict__ w,
                        const float* __restrict__ bias, float* __restrict__ out,
                        int HIN, int WIN, int HOUT, int WOUT)
{
    const int cob = blockIdx.y * CT;
    const int nb  = blockIdx.z;

    __shared__ __align__(16) float sw[CIN * 16 * CT];
    __shared__ float sb[CT];
    for (int i = threadIdx.x; i < CIN * 16 * CT; i += blockDim.x) {
        int ci = i / (16 * CT);
        int r  = i - ci * 16 * CT;
        int tap = r / CT, co = r - tap * CT;
        sw[i] = w[((size_t)ci * COUT + cob + co) * 16 + tap];
    }
    if (threadIdx.x < CT) sb[threadIdx.x] = bias[cob + threadIdx.x];
    __syncthreads();

    int sp = blockIdx.x * blockDim.x + threadIdx.x;
    if (sp >= HOUT * WOUT) return;
    int oh = sp / WOUT, ow = sp - oh * WOUT;

    const float* ib = in + (size_t)nb * CIN * HIN * WIN;
    float acc[CT];
    #pragma unroll
    for (int c = 0; c < CT; c++) acc[c] = sb[c];

    #pragma unroll
    for (int dkh = 0; dkh < 2; dkh++) {
        int kh = (oh & 1) + 2 * dkh;
        int t = oh - kh;
        if (t < 0) continue;
        int ih = t >> 1;
        if (ih >= HIN) continue;
        #pragma unroll
        for (int dkw = 0; dkw < 2; dkw++) {
            int kw = (ow & 1) + 2 * dkw;
            int u = ow - kw;
            if (u < 0) continue;
            int iw = u >> 1;
            if (iw >= WIN) continue;
            int tap = kh * 4 + kw;
            for (int ci = 0; ci < CIN; ci++) {
                float v = ib[(ci * HIN + ih) * WIN + iw];
                if (CT >= 4) {
                    const float4* wp = (const float4*)&sw[(ci * 16 + tap) * CT];
                    #pragma unroll
                    for (int c4 = 0; c4 < CT / 4; c4++) {
                        float4 wv = wp[c4];
                        acc[c4*4+0] = fmaf(v, wv.x, acc[c4*4+0]);
                        acc[c4*4+1] = fmaf(v, wv.y, acc[c4*4+1]);
                        acc[c4*4+2] = fmaf(v, wv.z, acc[c4*4+2]);
                        acc[c4*4+3] = fmaf(v, wv.w, acc[c4*4+3]);
                    }
                } else {
                    const float* wp = &sw[(ci * 16 + tap) * CT];
                    #pragma unroll
                    for (int c = 0; c < CT; c++) acc[c] = fmaf(v, wp[c], acc[c]);
                }
            }
        }
    }
    #pragma unroll
    for (int c = 0; c < CT; c++) {
        float a = acc[c];
        if (ACT == 1) a = a >= 0.f ? a : LRELU_SLOPE * a;
        if (ACT == 2) a = tanhf(a);
        out[(((size_t)nb * COUT + cob + c) * HOUT + oh) * WOUT + ow] = a;
    }
}

// ---------------- codebook squared norms ----------------
__global__ void cnorm_k(const float* __restrict__ cb)
{
    int c = blockIdx.x * blockDim.x + threadIdx.x;
    if (c < 512) {
        float s = 0.f;
        #pragma unroll
        for (int d = 0; d < 64; d++) {
            float v = cb[c * 64 + d];
            s = fmaf(v, v, s);
        }
        g_cnorm[c] = s;
    }
}

// ---------------- VQ: argmax(dot - 0.5*||c||^2), float4 smem reads ----------
__global__ void vq_k(const float* __restrict__ e5, const float* __restrict__ cb,
                     float* __restrict__ z)
{
    __shared__ __align__(16) float scb[128 * 64];
    __shared__ float scn[128];
    __shared__ float red[256];

    int n  = blockIdx.x * 256 + threadIdx.x;
    int b  = n / 900;
    int sp = n - b * 900;

    float lat[64];
    float fnorm = 0.f;
    #pragma unroll
    for (int d = 0; d < 64; d++) {
        float v = e5[((size_t)(b * 64 + d)) * 900 + sp];
        lat[d] = v;
        fnorm = fmaf(v, v, fnorm);
    }

    float best = -1e30f;
    int bi = 0;
    for (int cbase = 0; cbase < 512; cbase += 128) {
        const float4* src = (const float4*)(cb + cbase * 64);
        float4* dst = (float4*)scb;
        for (int i = threadIdx.x; i < 2048; i += 256) dst[i] = src[i];
        if (threadIdx.x < 128) scn[threadIdx.x] = g_cnorm[cbase + threadIdx.x];
        __syncthreads();

        for (int c = 0; c < 128; c++) {
            const float4* cp = (const float4*)&scb[c * 64];
            float d0 = 0.f, d1 = 0.f, d2 = 0.f, d3 = 0.f;
            #pragma unroll
            for (int q = 0; q < 16; q += 4) {
                float4 w0 = cp[q+0], w1 = cp[q+1], w2 = cp[q+2], w3 = cp[q+3];
                d0 = fmaf(lat[4*q+ 0], w0.x, d0); d0 = fmaf(lat[4*q+ 1], w0.y, d0);
                d0 = fmaf(lat[4*q+ 2], w0.z, d0); d0 = fmaf(lat[4*q+ 3], w0.w, d0);
                d1 = fmaf(lat[4*q+ 4], w1.x, d1); d1 = fmaf(lat[4*q+ 5], w1.y, d1);
                d1 = fmaf(lat[4*q+ 6], w1.z, d1); d1 = fmaf(lat[4*q+ 7], w1.w, d1);
                d2 = fmaf(lat[4*q+ 8], w2.x, d2); d2 = fmaf(lat[4*q+ 9], w2.y, d2);
                d2 = fmaf(lat[4*q+10], w2.z, d2); d2 = fmaf(lat[4*q+11], w2.w, d2);
                d3 = fmaf(lat[4*q+12], w3.x, d3); d3 = fmaf(lat[4*q+13], w3.y, d3);
                d3 = fmaf(lat[4*q+14], w3.z, d3); d3 = fmaf(lat[4*q+15], w3.w, d3);
            }
            float score = (d0 + d1) + (d2 + d3) - 0.5f * scn[c];
            if (score > best) { best = score; bi = cbase + c; }
        }
        __syncthreads();
    }

    const float* cq = cb + bi * 64;
    #pragma unroll
    for (int d = 0; d < 64; d++)
        z[((size_t)(b * 64 + d)) * 900 + sp] = cq[d];

    float d2v = fnorm - 2.f * best;
    red[threadIdx.x] = d2v;
    __syncthreads();
    for (int s = 128; s > 0; s >>= 1) {
        if (threadIdx.x < s) red[threadIdx.x] += red[threadIdx.x + s];
        __syncthreads();
    }
    if (threadIdx.x == 0) g_partial[blockIdx.x] = red[0];
}

// ---------------- deterministic loss finalize ----------------
__global__ void loss_fin(float* __restrict__ out, int out_size)
{
    __shared__ float red[256];
    float v = (threadIdx.x < 225) ? g_partial[threadIdx.x] : 0.f;
    red[threadIdx.x] = v;
    __syncthreads();
    for (int s = 128; s > 0; s >>= 1) {
        if (threadIdx.x < s) red[threadIdx.x] += red[threadIdx.x + s];
        __syncthreads();
    }
    if (threadIdx.x == 0)
        out[out_size - 1] = 1.25f * red[0] / 3686400.0f;
}

// ---------------- launch ----------------
extern "C" void kernel_launch(void* const* d_in, const int* in_sizes, int n_in,
                              void* d_out, int out_size)
{
    (void)in_sizes; (void)n_in;
    const float* x   = (const float*)d_in[0];
    const float* ew1 = (const float*)d_in[1];  const float* eb1 = (const float*)d_in[2];
    const float* ew2 = (const float*)d_in[3];  const float* eb2 = (const float*)d_in[4];
    const float* ew3 = (const float*)d_in[5];  const float* eb3 = (const float*)d_in[6];
    const float* ew4 = (const float*)d_in[7];  const float* eb4 = (const float*)d_in[8];
    const float* ew5 = (const float*)d_in[9];  const float* eb5 = (const float*)d_in[10];
    const float* dw1 = (const float*)d_in[11]; const float* db1 = (const float*)d_in[12];
    const float* dw2 = (const float*)d_in[13]; const float* db2 = (const float*)d_in[14];
    const float* dw3 = (const float*)d_in[15]; const float* db3 = (const float*)d_in[16];
    const float* dw4 = (const float*)d_in[17]; const float* db4 = (const float*)d_in[18];
    const float* cbk = (const float*)d_in[19];
    float* out = (float*)d_out;

    float *bufA, *bufB;
    cudaGetSymbolAddress((void**)&bufA, g_bufA);
    cudaGetSymbolAddress((void**)&bufB, g_bufB);

    const int B = 64;

    // ---- encoder ----
    // conv1: [64,1,256,256] -> [64,8,127,127]   CT=8
    conv_t<1, 8, 8, 4, 2, 0, 1><<<dim3((127*127 + 255)/256, 1, B), 256>>>(x, ew1, eb1, bufA, 256, 256, 127, 127);
    // conv2: -> [64,16,62,62]   CT=16
    conv_t<8, 16, 16, 4, 2, 0, 1><<<dim3((62*62 + 255)/256, 1, B), 256>>>(bufA, ew2, eb2, bufB, 127, 127, 62, 62);
    // conv3: -> [64,32,30,30]   CT=32
    conv_t<16, 32, 32, 4, 2, 0, 1><<<dim3((900 + 127)/128, 1, B), 128>>>(bufB, ew3, eb3, bufA, 62, 62, 30, 30);
    // conv4: 3x3 p1 -> [64,32,30,30]   CT=32
    conv_t<32, 32, 32, 3, 1, 1, 1><<<dim3((900 + 127)/128, 1, B), 128>>>(bufA, ew4, eb4, bufB, 30, 30, 30, 30);
    // conv5: 1x1 -> [64,64,30,30]   CT=32, 2 tiles
    conv_t<32, 64, 32, 1, 1, 0, 1><<<dim3((900 + 127)/128, 2, B), 128>>>(bufB, ew5, eb5, bufA, 30, 30, 30, 30);

    // ---- VQ ----
    cnorm_k<<<2, 256>>>(cbk);
    vq_k<<<225, 256>>>(bufA, cbk, bufB);

    // ---- decoder ----
    // d1: 3x3 p1, 64->32   CT=16, 2 tiles
    conv_t<64, 32, 16, 3, 1, 1, 1><<<dim3((900 + 127)/128, 2, B), 128>>>(bufB, dw1, db1, bufA, 30, 30, 30, 30);
    // t2: 32->16, 30 -> 63   CT=16
    tconv_t<32, 16, 16, 1><<<dim3((63*63 + 255)/256, 1, B), 256>>>(bufA, dw2, db2, bufB, 30, 30, 63, 63);
    // t3: 16->8, 63 -> 129   CT=8
    tconv_t<16, 8, 8, 1><<<dim3((129*129 + 255)/256, 1, B), 256>>>(bufB, dw3, db3, bufA, 63, 63, 129, 129);
    // t4: 8->1, 129 -> 260, tanh   CT=1
    tconv_t<8, 1, 1, 2><<<dim3((260*260 + 255)/256, 1, B), 256>>>(bufA, dw4, db4, out, 129, 129, 260, 260);

    // ---- loss scalar ----
    loss_fin<<<1, 256>>>(out, out_size);
}

// round 3
// speedup vs baseline: 2.8136x; 1.2354x over previous
#include <cuda_runtime.h>
#include <math.h>

// ---------------- static scratch (no allocations allowed) ----------------
__device__ float g_bufA[8520192];
__device__ float g_bufB[8520192];
__device__ float g_cnorm[512];
__device__ float g_partial[256];

#define LRELU_SLOPE 0.01f

// ================= conv2d: 2D register tile (SPT spatial x CT channels) ======
// Each thread: SPT consecutive ow positions at one oh, CT output channels.
// Weights staged in shared as [tap][co]; inputs loaded once per row-tap with
// sliding-window reuse. OOB inputs zero-filled (valid for pad-0 overrun + pad>0).
template<int CIN, int COUT, int CT, int K, int S, int P, int SPT, int ACT>
__global__ void conv_t2(const float* __restrict__ in, const float* __restrict__ w,
                        const float* __restrict__ bias, float* __restrict__ out,
                        int HIN, int WIN, int HOUT, int WOUT, int GW)
{
    const int cob = blockIdx.y * CT;
    const int nb  = blockIdx.z;

    __shared__ __align__(16) float sw[CIN * K * K * CT];
    __shared__ float sb[CT];
    for (int i = threadIdx.x; i < CIN * K * K * CT; i += blockDim.x) {
        int tap = i / CT, co = i - tap * CT;
        sw[i] = w[(size_t)(cob + co) * CIN * K * K + tap];
    }
    if (threadIdx.x < CT) sb[threadIdx.x] = bias[cob + threadIdx.x];
    __syncthreads();

    int g = blockIdx.x * blockDim.x + threadIdx.x;
    if (g >= HOUT * GW) return;
    int oh  = g / GW;
    int ow0 = (g - oh * GW) * SPT;

    const float* ib = in + (size_t)nb * CIN * HIN * WIN;

    float acc[SPT][CT];
    #pragma unroll
    for (int s = 0; s < SPT; s++)
        #pragma unroll
        for (int c = 0; c < CT; c++) acc[s][c] = sb[c];

    constexpr int NIW = (SPT - 1) * S + K;
    const int iwb = ow0 * S - P;

    for (int ci = 0; ci < CIN; ci++) {
        #pragma unroll
        for (int kh = 0; kh < K; kh++) {
            int ih = oh * S - P + kh;
            bool rv = ((unsigned)ih < (unsigned)HIN);
            const float* rp = ib + ((size_t)ci * HIN + ih) * WIN;
            float inv[NIW];
            #pragma unroll
            for (int j = 0; j < NIW; j++) {
                int iw = iwb + j;
                inv[j] = (rv && iw >= 0 && iw < WIN) ? rp[iw] : 0.f;
            }
            #pragma unroll
            for (int kw = 0; kw < K; kw++) {
                #pragma unroll
                for (int c4 = 0; c4 < CT / 4; c4++) {
                    float4 wv = *(const float4*)&sw[((ci * K + kh) * K + kw) * CT + c4 * 4];
                    #pragma unroll
                    for (int s = 0; s < SPT; s++) {
                        float v = inv[s * S + kw];
                        acc[s][c4*4+0] = fmaf(v, wv.x, acc[s][c4*4+0]);
                        acc[s][c4*4+1] = fmaf(v, wv.y, acc[s][c4*4+1]);
                        acc[s][c4*4+2] = fmaf(v, wv.z, acc[s][c4*4+2]);
                        acc[s][c4*4+3] = fmaf(v, wv.w, acc[s][c4*4+3]);
                    }
                }
            }
        }
    }

    #pragma unroll
    for (int s = 0; s < SPT; s++) {
        int ow = ow0 + s;
        if (ow >= WOUT) continue;
        #pragma unroll
        for (int c = 0; c < CT; c++) {
            float a = acc[s][c];
            if (ACT == 1) a = a >= 0.f ? a : LRELU_SLOPE * a;
            out[(((size_t)nb * COUT + cob + c) * HOUT + oh) * WOUT + ow] = a;
        }
    }
}

// ============ transposed conv k=4 s=2 (gather), 2D register tile ============
// SPT even; ow0 even. SPT outputs per row need only SPT/2+1 inputs (parity).
// weights [CIN, COUT, 4, 4]; output s uses tap kw=(s&1)+2*dkw at inv[s/2+1-dkw].
template<int CIN, int COUT, int CT, int SPT, int ACT>
__global__ void tconv_t2(const float* __restrict__ in, const float* __restrict__ w,
                         const float* __restrict__ bias, float* __restrict__ out,
                         int HIN, int WIN, int HOUT, int WOUT, int GW)
{
    const int cob = blockIdx.y * CT;
    const int nb  = blockIdx.z;

    __shared__ __align__(16) float sw[CIN * 16 * CT];
    __shared__ float sb[CT];
    for (int i = threadIdx.x; i < CIN * 16 * CT; i += blockDim.x) {
        int ci = i / (16 * CT);
        int r  = i - ci * 16 * CT;
        int tap = r / CT, co = r - tap * CT;
        sw[i] = w[((size_t)ci * COUT + cob + co) * 16 + tap];
    }
    if (threadIdx.x < CT) sb[threadIdx.x] = bias[cob + threadIdx.x];
    __syncthreads();

    int g = blockIdx.x * blockDim.x + threadIdx.x;
    if (g >= HOUT * GW) return;
    int oh  = g / GW;
    int ow0 = (g - oh * GW) * SPT;
    const int hpar = oh & 1;

    const float* ib = in + (size_t)nb * CIN * HIN * WIN;

    float acc[SPT][CT];
    #pragma unroll
    for (int s = 0; s < SPT; s++)
        #pragma unroll
        for (int c = 0; c < CT; c++) acc[s][c] = sb[c];

    constexpr int NIW = SPT / 2 + 1;
    const int iwb = (ow0 >> 1) - 1;

    for (int ci = 0; ci < CIN; ci++) {
        #pragma unroll
        for (int dkh = 0; dkh < 2; dkh++) {
            int kh = hpar + 2 * dkh;
            int t  = oh - kh;
            int ih = t >> 1;
            bool rv = (t >= 0) && (ih < HIN);
            const float* rp = ib + ((size_t)ci * HIN + ih) * WIN;
            float inv[NIW];
            #pragma unroll
            for (int j = 0; j < NIW; j++) {
                int iw = iwb + j;
                inv[j] = (rv && iw >= 0 && iw < WIN) ? rp[iw] : 0.f;
            }
            #pragma unroll
            for (int dkw = 0; dkw < 2; dkw++) {
                #pragma unroll
                for (int wpar = 0; wpar < 2; wpar++) {
                    int tap = kh * 4 + wpar + 2 * dkw;
                    if (CT >= 4) {
                        #pragma unroll
                        for (int c4 = 0; c4 < CT / 4; c4++) {
                            float4 wv = *(const float4*)&sw[(ci * 16 + tap) * CT + c4 * 4];
                            #pragma unroll
                            for (int s = wpar; s < SPT; s += 2) {
                                float v = inv[s / 2 + 1 - dkw];
                                acc[s][c4*4+0] = fmaf(v, wv.x, acc[s][c4*4+0]);
                                acc[s][c4*4+1] = fmaf(v, wv.y, acc[s][c4*4+1]);
                                acc[s][c4*4+2] = fmaf(v, wv.z, acc[s][c4*4+2]);
                                acc[s][c4*4+3] = fmaf(v, wv.w, acc[s][c4*4+3]);
                            }
                        }
                    } else {
                        #pragma unroll
                        for (int c = 0; c < CT; c++) {
                            float wa = sw[(ci * 16 + tap) * CT + c];
                            #pragma unroll
                            for (int s = wpar; s < SPT; s += 2)
                                acc[s][c] = fmaf(inv[s / 2 + 1 - dkw], wa, acc[s][c]);
                        }
                    }
                }
            }
        }
    }

    #pragma unroll
    for (int s = 0; s < SPT; s++) {
        int ow = ow0 + s;
        if (ow >= WOUT) continue;
        #pragma unroll
        for (int c = 0; c < CT; c++) {
            float a = acc[s][c];
            if (ACT == 1) a = a >= 0.f ? a : LRELU_SLOPE * a;
            if (ACT == 2) a = tanhf(a);
            out[(((size_t)nb * COUT + cob + c) * HOUT + oh) * WOUT + ow] = a;
        }
    }
}

// ---------------- codebook squared norms ----------------
__global__ void cnorm_k(const float* __restrict__ cb)
{
    int c = blockIdx.x * blockDim.x + threadIdx.x;
    if (c < 512) {
        float s = 0.f;
        #pragma unroll
        for (int d = 0; d < 64; d++) {
            float v = cb[c * 64 + d];
            s = fmaf(v, v, s);
        }
        g_cnorm[c] = s;
    }
}

// ---------------- VQ: argmax(dot - 0.5*||c||^2), float4 smem reads ----------
__global__ void vq_k(const float* __restrict__ e5, const float* __restrict__ cb,
                     float* __restrict__ z)
{
    __shared__ __align__(16) float scb[128 * 64];
    __shared__ float scn[128];
    __shared__ float red[256];

    int n  = blockIdx.x * 256 + threadIdx.x;
    int b  = n / 900;
    int sp = n - b * 900;

    float lat[64];
    float fnorm = 0.f;
    #pragma unroll
    for (int d = 0; d < 64; d++) {
        float v = e5[((size_t)(b * 64 + d)) * 900 + sp];
        lat[d] = v;
        fnorm = fmaf(v, v, fnorm);
    }

    float best = -1e30f;
    int bi = 0;
    for (int cbase = 0; cbase < 512; cbase += 128) {
        const float4* src = (const float4*)(cb + cbase * 64);
        float4* dst = (float4*)scb;
        for (int i = threadIdx.x; i < 2048; i += 256) dst[i] = src[i];
        if (threadIdx.x < 128) scn[threadIdx.x] = g_cnorm[cbase + threadIdx.x];
        __syncthreads();

        for (int c = 0; c < 128; c++) {
            const float4* cp = (const float4*)&scb[c * 64];
            float d0 = 0.f, d1 = 0.f, d2 = 0.f, d3 = 0.f;
            #pragma unroll
            for (int q = 0; q < 16; q += 4) {
                float4 w0 = cp[q+0], w1 = cp[q+1], w2 = cp[q+2], w3 = cp[q+3];
                d0 = fmaf(lat[4*q+ 0], w0.x, d0); d0 = fmaf(lat[4*q+ 1], w0.y, d0);
                d0 = fmaf(lat[4*q+ 2], w0.z, d0); d0 = fmaf(lat[4*q+ 3], w0.w, d0);
                d1 = fmaf(lat[4*q+ 4], w1.x, d1); d1 = fmaf(lat[4*q+ 5], w1.y, d1);
                d1 = fmaf(lat[4*q+ 6], w1.z, d1); d1 = fmaf(lat[4*q+ 7], w1.w, d1);
                d2 = fmaf(lat[4*q+ 8], w2.x, d2); d2 = fmaf(lat[4*q+ 9], w2.y, d2);
                d2 = fmaf(lat[4*q+10], w2.z, d2); d2 = fmaf(lat[4*q+11], w2.w, d2);
                d3 = fmaf(lat[4*q+12], w3.x, d3); d3 = fmaf(lat[4*q+13], w3.y, d3);
                d3 = fmaf(lat[4*q+14], w3.z, d3); d3 = fmaf(lat[4*q+15], w3.w, d3);
            }
            float score = (d0 + d1) + (d2 + d3) - 0.5f * scn[c];
            if (score > best) { best = score; bi = cbase + c; }
        }
        __syncthreads();
    }

    const float* cq = cb + bi * 64;
    #pragma unroll
    for (int d = 0; d < 64; d++)
        z[((size_t)(b * 64 + d)) * 900 + sp] = cq[d];

    float d2v = fnorm - 2.f * best;
    red[threadIdx.x] = d2v;
    __syncthreads();
    for (int s = 128; s > 0; s >>= 1) {
        if (threadIdx.x < s) red[threadIdx.x] += red[threadIdx.x + s];
        __syncthreads();
    }
    if (threadIdx.x == 0) g_partial[blockIdx.x] = red[0];
}

// ---------------- deterministic loss finalize ----------------
__global__ void loss_fin(float* __restrict__ out, int out_size)
{
    __shared__ float red[256];
    float v = (threadIdx.x < 225) ? g_partial[threadIdx.x] : 0.f;
    red[threadIdx.x] = v;
    __syncthreads();
    for (int s = 128; s > 0; s >>= 1) {
        if (threadIdx.x < s) red[threadIdx.x] += red[threadIdx.x + s];
        __syncthreads();
    }
    if (threadIdx.x == 0)
        out[out_size - 1] = 1.25f * red[0] / 3686400.0f;
}

// ---------------- launch ----------------
extern "C" void kernel_launch(void* const* d_in, const int* in_sizes, int n_in,
                              void* d_out, int out_size)
{
    (void)in_sizes; (void)n_in;
    const float* x   = (const float*)d_in[0];
    const float* ew1 = (const float*)d_in[1];  const float* eb1 = (const float*)d_in[2];
    const float* ew2 = (const float*)d_in[3];  const float* eb2 = (const float*)d_in[4];
    const float* ew3 = (const float*)d_in[5];  const float* eb3 = (const float*)d_in[6];
    const float* ew4 = (const float*)d_in[7];  const float* eb4 = (const float*)d_in[8];
    const float* ew5 = (const float*)d_in[9];  const float* eb5 = (const float*)d_in[10];
    const float* dw1 = (const float*)d_in[11]; const float* db1 = (const float*)d_in[12];
    const float* dw2 = (const float*)d_in[13]; const float* db2 = (const float*)d_in[14];
    const float* dw3 = (const float*)d_in[15]; const float* db3 = (const float*)d_in[16];
    const float* dw4 = (const float*)d_in[17]; const float* db4 = (const float*)d_in[18];
    const float* cbk = (const float*)d_in[19];
    float* out = (float*)d_out;

    float *bufA, *bufB;
    cudaGetSymbolAddress((void**)&bufA, g_bufA);
    cudaGetSymbolAddress((void**)&bufB, g_bufB);

    const int B = 64;

    // ---- encoder ----
    // conv1: [64,1,256,256] -> [64,8,127,127]  SPT=4 CT=8, GW=32, groups=4064
    conv_t2<1, 8, 8, 4, 2, 0, 4, 1><<<dim3(32, 1, B), 128>>>(x, ew1, eb1, bufA, 256, 256, 127, 127, 32);
    // conv2: -> [64,16,62,62]  SPT=4 CT=16, GW=16, groups=992
    conv_t2<8, 16, 16, 4, 2, 0, 4, 1><<<dim3(8, 1, B), 128>>>(bufA, ew2, eb2, bufB, 127, 127, 62, 62, 16);
    // conv3: -> [64,32,30,30]  SPT=5 CT=8 y=4, GW=6, groups=180
    conv_t2<16, 32, 8, 4, 2, 0, 5, 1><<<dim3(2, 4, B), 96>>>(bufB, ew3, eb3, bufA, 62, 62, 30, 30, 6);
    // conv4: 3x3 p1 -> [64,32,30,30]  SPT=5 CT=8 y=4
    conv_t2<32, 32, 8, 3, 1, 1, 5, 1><<<dim3(2, 4, B), 96>>>(bufA, ew4, eb4, bufB, 30, 30, 30, 30, 6);
    // conv5: 1x1 -> [64,64,30,30]  SPT=4 CT=16 y=4, GW=8, groups=240
    conv_t2<32, 64, 16, 1, 1, 0, 4, 1><<<dim3(2, 4, B), 128>>>(bufB, ew5, eb5, bufA, 30, 30, 30, 30, 8);

    // ---- VQ ----
    cnorm_k<<<2, 256>>>(cbk);
    vq_k<<<225, 256>>>(bufA, cbk, bufB);

    // ---- decoder ----
    // d1: 3x3 p1, 64->32  SPT=5 CT=8 y=4
    conv_t2<64, 32, 8, 3, 1, 1, 5, 1><<<dim3(2, 4, B), 96>>>(bufB, dw1, db1, bufA, 30, 30, 30, 30, 6);
    // t2: 32->16, 30 -> 63  SPT=4 CT=16, GW=16, groups=1008
    tconv_t2<32, 16, 16, 4, 1><<<dim3(8, 1, B), 128>>>(bufA, dw2, db2, bufB, 30, 30, 63, 63, 16);
    // t3: 16->8, 63 -> 129  SPT=4 CT=8, GW=33, groups=4257
    tconv_t2<16, 8, 8, 4, 1><<<dim3(34, 1, B), 128>>>(bufB, dw3, db3, bufA, 63, 63, 129, 129, 33);
    // t4: 8->1, 129 -> 260, tanh  SPT=8 CT=1, GW=33, groups=8580
    tconv_t2<8, 1, 1, 8, 2><<<dim3(68, 1, B), 128>>>(bufA, dw4, db4, out, 129, 129, 260, 260, 33);

    // ---- loss scalar ----
    loss_fin<<<1, 256>>>(out, out_size);
}

// round 4
// speedup vs baseline: 2.8771x; 1.0226x over previous
#include <cuda_runtime.h>
#include <math.h>

// ---------------- static scratch (no allocations allowed) ----------------
__device__ float g_bufA[8520192];
__device__ float g_bufB[8520192];
__device__ float g_cnorm[512];
__device__ float g_partial[256];

#define LRELU_SLOPE 0.01f

// ================= conv2d: 2D register tile (SPT spatial x CT channels) ======
template<int CIN, int COUT, int CT, int K, int S, int P, int SPT, int ACT>
__global__ void __launch_bounds__(128)
conv_t2(const float* __restrict__ in, const float* __restrict__ w,
        const float* __restrict__ bias, float* __restrict__ out,
        int HIN, int WIN, int HOUT, int WOUT, int GW)
{
    const int cob = blockIdx.y * CT;
    const int nb  = blockIdx.z;

    __shared__ __align__(16) float sw[CIN * K * K * CT];
    __shared__ float sb[CT];
    for (int i = threadIdx.x; i < CIN * K * K * CT; i += blockDim.x) {
        int tap = i / CT, co = i - tap * CT;
        sw[i] = w[(size_t)(cob + co) * CIN * K * K + tap];
    }
    if (threadIdx.x < CT) sb[threadIdx.x] = bias[cob + threadIdx.x];
    __syncthreads();

    int g = blockIdx.x * blockDim.x + threadIdx.x;
    if (g >= HOUT * GW) return;
    int oh  = g / GW;
    int ow0 = (g - oh * GW) * SPT;

    const float* ib = in + (size_t)nb * CIN * HIN * WIN;

    float acc[SPT][CT];
    #pragma unroll
    for (int s = 0; s < SPT; s++)
        #pragma unroll
        for (int c = 0; c < CT; c++) acc[s][c] = sb[c];

    constexpr int NIW = (SPT - 1) * S + K;
    const int iwb = ow0 * S - P;

    for (int ci = 0; ci < CIN; ci++) {
        #pragma unroll
        for (int kh = 0; kh < K; kh++) {
            int ih = oh * S - P + kh;
            bool rv = ((unsigned)ih < (unsigned)HIN);
            const float* rp = ib + ((size_t)ci * HIN + ih) * WIN;
            float inv[NIW];
            #pragma unroll
            for (int j = 0; j < NIW; j++) {
                int iw = iwb + j;
                inv[j] = (rv && iw >= 0 && iw < WIN) ? rp[iw] : 0.f;
            }
            #pragma unroll
            for (int kw = 0; kw < K; kw++) {
                #pragma unroll
                for (int c4 = 0; c4 < CT / 4; c4++) {
                    float4 wv = *(const float4*)&sw[((ci * K + kh) * K + kw) * CT + c4 * 4];
                    #pragma unroll
                    for (int s = 0; s < SPT; s++) {
                        float v = inv[s * S + kw];
                        acc[s][c4*4+0] = fmaf(v, wv.x, acc[s][c4*4+0]);
                        acc[s][c4*4+1] = fmaf(v, wv.y, acc[s][c4*4+1]);
                        acc[s][c4*4+2] = fmaf(v, wv.z, acc[s][c4*4+2]);
                        acc[s][c4*4+3] = fmaf(v, wv.w, acc[s][c4*4+3]);
                    }
                }
            }
        }
    }

    #pragma unroll
    for (int s = 0; s < SPT; s++) {
        int ow = ow0 + s;
        if (ow >= WOUT) continue;
        #pragma unroll
        for (int c = 0; c < CT; c++) {
            float a = acc[s][c];
            if (ACT == 1) a = a >= 0.f ? a : LRELU_SLOPE * a;
            out[(((size_t)nb * COUT + cob + c) * HOUT + oh) * WOUT + ow] = a;
        }
    }
}

// ============ transposed conv k=4 s=2 (gather), 2D register tile ============
template<int CIN, int COUT, int CT, int SPT, int ACT>
__global__ void __launch_bounds__(128)
tconv_t2(const float* __restrict__ in, const float* __restrict__ w,
         const float* __restrict__ bias, float* __restrict__ out,
         int HIN, int WIN, int HOUT, int WOUT, int GW)
{
    const int cob = blockIdx.y * CT;
    const int nb  = blockIdx.z;

    __shared__ __align__(16) float sw[CIN * 16 * CT];
    __shared__ float sb[CT];
    for (int i = threadIdx.x; i < CIN * 16 * CT; i += blockDim.x) {
        int ci = i / (16 * CT);
        int r  = i - ci * 16 * CT;
        int tap = r / CT, co = r - tap * CT;
        sw[i] = w[((size_t)ci * COUT + cob + co) * 16 + tap];
    }
    if (threadIdx.x < CT) sb[threadIdx.x] = bias[cob + threadIdx.x];
    __syncthreads();

    int g = blockIdx.x * blockDim.x + threadIdx.x;
    if (g >= HOUT * GW) return;
    int oh  = g / GW;
    int ow0 = (g - oh * GW) * SPT;
    const int hpar = oh & 1;

    const float* ib = in + (size_t)nb * CIN * HIN * WIN;

    float acc[SPT][CT];
    #pragma unroll
    for (int s = 0; s < SPT; s++)
        #pragma unroll
        for (int c = 0; c < CT; c++) acc[s][c] = sb[c];

    constexpr int NIW = SPT / 2 + 1;
    const int iwb = (ow0 >> 1) - 1;

    for (int ci = 0; ci < CIN; ci++) {
        #pragma unroll
        for (int dkh = 0; dkh < 2; dkh++) {
            int kh = hpar + 2 * dkh;
            int t  = oh - kh;
            int ih = t >> 1;
            bool rv = (t >= 0) && (ih < HIN);
            const float* rp = ib + ((size_t)ci * HIN + ih) * WIN;
            float inv[NIW];
            #pragma unroll
            for (int j = 0; j < NIW; j++) {
                int iw = iwb + j;
                inv[j] = (rv && iw >= 0 && iw < WIN) ? rp[iw] : 0.f;
            }
            #pragma unroll
            for (int dkw = 0; dkw < 2; dkw++) {
                #pragma unroll
                for (int wpar = 0; wpar < 2; wpar++) {
                    int tap = kh * 4 + wpar + 2 * dkw;
                    if (CT >= 4) {
                        #pragma unroll
                        for (int c4 = 0; c4 < CT / 4; c4++) {
                            float4 wv = *(const float4*)&sw[(ci * 16 + tap) * CT + c4 * 4];
                            #pragma unroll
                            for (int s = wpar; s < SPT; s += 2) {
                                float v = inv[s / 2 + 1 - dkw];
                                acc[s][c4*4+0] = fmaf(v, wv.x, acc[s][c4*4+0]);
                                acc[s][c4*4+1] = fmaf(v, wv.y, acc[s][c4*4+1]);
                                acc[s][c4*4+2] = fmaf(v, wv.z, acc[s][c4*4+2]);
                                acc[s][c4*4+3] = fmaf(v, wv.w, acc[s][c4*4+3]);
                            }
                        }
                    } else {
                        #pragma unroll
                        for (int c = 0; c < CT; c++) {
                            float wa = sw[(ci * 16 + tap) * CT + c];
                            #pragma unroll
                            for (int s = wpar; s < SPT; s += 2)
                                acc[s][c] = fmaf(inv[s / 2 + 1 - dkw], wa, acc[s][c]);
                        }
                    }
                }
            }
        }
    }

    #pragma unroll
    for (int s = 0; s < SPT; s++) {
        int ow = ow0 + s;
        if (ow >= WOUT) continue;
        #pragma unroll
        for (int c = 0; c < CT; c++) {
            float a = acc[s][c];
            if (ACT == 1) a = a >= 0.f ? a : LRELU_SLOPE * a;
            if (ACT == 2) a = tanhf(a);
            out[(((size_t)nb * COUT + cob + c) * HOUT + oh) * WOUT + ow] = a;
        }
    }
}

// ---------------- codebook squared norms ----------------
__global__ void cnorm_k(const float* __restrict__ cb)
{
    int c = blockIdx.x * blockDim.x + threadIdx.x;
    if (c < 512) {
        float s = 0.f;
        #pragma unroll
        for (int d = 0; d < 64; d++) {
            float v = cb[c * 64 + d];
            s = fmaf(v, v, s);
        }
        g_cnorm[c] = s;
    }
}

// ---------------- VQ: argmax(dot - 0.5*||c||^2), float4 smem reads ----------
__global__ void vq_k(const float* __restrict__ e5, const float* __restrict__ cb,
                     float* __restrict__ z)
{
    __shared__ __align__(16) float scb[128 * 64];
    __shared__ float scn[128];
    __shared__ float red[256];

    int n  = blockIdx.x * 256 + threadIdx.x;
    int b  = n / 900;
    int sp = n - b * 900;

    float lat[64];
    float fnorm = 0.f;
    #pragma unroll
    for (int d = 0; d < 64; d++) {
        float v = e5[((size_t)(b * 64 + d)) * 900 + sp];
        lat[d] = v;
        fnorm = fmaf(v, v, fnorm);
    }

    float best = -1e30f;
    int bi = 0;
    for (int cbase = 0; cbase < 512; cbase += 128) {
        const float4* src = (const float4*)(cb + cbase * 64);
        float4* dst = (float4*)scb;
        for (int i = threadIdx.x; i < 2048; i += 256) dst[i] = src[i];
        if (threadIdx.x < 128) scn[threadIdx.x] = g_cnorm[cbase + threadIdx.x];
        __syncthreads();

        for (int c = 0; c < 128; c++) {
            const float4* cp = (const float4*)&scb[c * 64];
            float d0 = 0.f, d1 = 0.f, d2 = 0.f, d3 = 0.f;
            #pragma unroll
            for (int q = 0; q < 16; q += 4) {
                float4 w0 = cp[q+0], w1 = cp[q+1], w2 = cp[q+2], w3 = cp[q+3];
                d0 = fmaf(lat[4*q+ 0], w0.x, d0); d0 = fmaf(lat[4*q+ 1], w0.y, d0);
                d0 = fmaf(lat[4*q+ 2], w0.z, d0); d0 = fmaf(lat[4*q+ 3], w0.w, d0);
                d1 = fmaf(lat[4*q+ 4], w1.x, d1); d1 = fmaf(lat[4*q+ 5], w1.y, d1);
                d1 = fmaf(lat[4*q+ 6], w1.z, d1); d1 = fmaf(lat[4*q+ 7], w1.w, d1);
                d2 = fmaf(lat[4*q+ 8], w2.x, d2); d2 = fmaf(lat[4*q+ 9], w2.y, d2);
                d2 = fmaf(lat[4*q+10], w2.z, d2); d2 = fmaf(lat[4*q+11], w2.w, d2);
                d3 = fmaf(lat[4*q+12], w3.x, d3); d3 = fmaf(lat[4*q+13], w3.y, d3);
                d3 = fmaf(lat[4*q+14], w3.z, d3); d3 = fmaf(lat[4*q+15], w3.w, d3);
            }
            float score = (d0 + d1) + (d2 + d3) - 0.5f * scn[c];
            if (score > best) { best = score; bi = cbase + c; }
        }
        __syncthreads();
    }

    const float* cq = cb + bi * 64;
    #pragma unroll
    for (int d = 0; d < 64; d++)
        z[((size_t)(b * 64 + d)) * 900 + sp] = cq[d];

    float d2v = fnorm - 2.f * best;
    red[threadIdx.x] = d2v;
    __syncthreads();
    for (int s = 128; s > 0; s >>= 1) {
        if (threadIdx.x < s) red[threadIdx.x] += red[threadIdx.x + s];
        __syncthreads();
    }
    if (threadIdx.x == 0) g_partial[blockIdx.x] = red[0];
}

// ---------------- deterministic loss finalize ----------------
__global__ void loss_fin(float* __restrict__ out, int out_size)
{
    __shared__ float red[256];
    float v = (threadIdx.x < 225) ? g_partial[threadIdx.x] : 0.f;
    red[threadIdx.x] = v;
    __syncthreads();
    for (int s = 128; s > 0; s >>= 1) {
        if (threadIdx.x < s) red[threadIdx.x] += red[threadIdx.x + s];
        __syncthreads();
    }
    if (threadIdx.x == 0)
        out[out_size - 1] = 1.25f * red[0] / 3686400.0f;
}

// ---------------- launch ----------------
extern "C" void kernel_launch(void* const* d_in, const int* in_sizes, int n_in,
                              void* d_out, int out_size)
{
    (void)in_sizes; (void)n_in;
    const float* x   = (const float*)d_in[0];
    const float* ew1 = (const float*)d_in[1];  const float* eb1 = (const float*)d_in[2];
    const float* ew2 = (const float*)d_in[3];  const float* eb2 = (const float*)d_in[4];
    const float* ew3 = (const float*)d_in[5];  const float* eb3 = (const float*)d_in[6];
    const float* ew4 = (const float*)d_in[7];  const float* eb4 = (const float*)d_in[8];
    const float* ew5 = (const float*)d_in[9];  const float* eb5 = (const float*)d_in[10];
    const float* dw1 = (const float*)d_in[11]; const float* db1 = (const float*)d_in[12];
    const float* dw2 = (const float*)d_in[13]; const float* db2 = (const float*)d_in[14];
    const float* dw3 = (const float*)d_in[15]; const float* db3 = (const float*)d_in[16];
    const float* dw4 = (const float*)d_in[17]; const float* db4 = (const float*)d_in[18];
    const float* cbk = (const float*)d_in[19];
    float* out = (float*)d_out;

    float *bufA, *bufB;
    cudaGetSymbolAddress((void**)&bufA, g_bufA);
    cudaGetSymbolAddress((void**)&bufB, g_bufB);

    const int B = 64;

    // ---- encoder ----
    // conv1: [64,1,256,256] -> [64,8,127,127]  SPT=4 CT=8, GW=32
    conv_t2<1, 8, 8, 4, 2, 0, 4, 1><<<dim3(32, 1, B), 128>>>(x, ew1, eb1, bufA, 256, 256, 127, 127, 32);
    // conv2: -> [64,16,62,62]  SPT=2 CT=16, GW=31, groups=1922 -> 123K threads
    conv_t2<8, 16, 16, 4, 2, 0, 2, 1><<<dim3(16, 1, B), 128>>>(bufA, ew2, eb2, bufB, 127, 127, 62, 62, 31);
    // conv3: -> [64,32,30,30]  SPT=3 CT=8 y=4, GW=10, groups=300 -> 77K threads
    conv_t2<16, 32, 8, 4, 2, 0, 3, 1><<<dim3(3, 4, B), 128>>>(bufB, ew3, eb3, bufA, 62, 62, 30, 30, 10);
    // conv4: 3x3 p1 -> [64,32,30,30]  SPT=3 CT=8 y=4
    conv_t2<32, 32, 8, 3, 1, 1, 3, 1><<<dim3(3, 4, B), 128>>>(bufA, ew4, eb4, bufB, 30, 30, 30, 30, 10);
    // conv5: 1x1 -> [64,64,30,30]  SPT=3 CT=16 y=4, GW=10
    conv_t2<32, 64, 16, 1, 1, 0, 3, 1><<<dim3(3, 4, B), 128>>>(bufB, ew5, eb5, bufA, 30, 30, 30, 30, 10);

    // ---- VQ ----
    cnorm_k<<<2, 256>>>(cbk);
    vq_k<<<225, 256>>>(bufA, cbk, bufB);

    // ---- decoder ----
    // d1: 3x3 p1, 64->32  SPT=3 CT=8 y=4
    conv_t2<64, 32, 8, 3, 1, 1, 3, 1><<<dim3(3, 4, B), 128>>>(bufB, dw1, db1, bufA, 30, 30, 30, 30, 10);
    // t2: 32->16, 30 -> 63  SPT=4 CT=8 y=2, GW=16, groups=1008 -> 129K threads
    tconv_t2<32, 16, 8, 4, 1><<<dim3(8, 2, B), 128>>>(bufA, dw2, db2, bufB, 30, 30, 63, 63, 16);
    // t3: 16->8, 63 -> 129  SPT=4 CT=8, GW=33, groups=4257 -> 272K threads
    tconv_t2<16, 8, 8, 4, 1><<<dim3(34, 1, B), 128>>>(bufB, dw3, db3, bufA, 63, 63, 129, 129, 33);
    // t4: 8->1, 129 -> 260, tanh  SPT=8 CT=1, GW=33
    tconv_t2<8, 1, 1, 8, 2><<<dim3(68, 1, B), 128>>>(bufA, dw4, db4, out, 129, 129, 260, 260, 33);

    // ---- loss scalar ----
    loss_fin<<<1, 256>>>(out, out_size);
}